// round 6
// baseline (speedup 1.0000x reference)
#include <cuda_runtime.h>
#include <cuda_bf16.h>
#include <mma.h>
#include <math.h>

using namespace nvcuda;

// ---------------------------------------------------------------------------
// Transformer-XL forward — tf32 tensor-core GEMMs, cp.async double buffered,
// producer-side tf32 rounding (no in-loop cvt). bf16 logits GEMM (loss path).
// ---------------------------------------------------------------------------

#define QLENC   512
#define KLENC   1024
#define BSZC    8
#define NHEADC  16
#define DHEADC  64
#define DMODELC 1024
#define DINNERC 4096
#define NTOKC   32000
#define NLAYERC 6
#define NT      4096
#define KT      8192

typedef __nv_bfloat16 bf;

__device__ __forceinline__ float tf32r(float x) {
    float r;
    asm("cvt.rna.tf32.f32 %0, %1;" : "=f"(r) : "f"(x));
    return r;
}

// ------------------------- scratch (device globals) ------------------------
__device__ float g_core [NT * DMODELC];    // exact fp32 (residual / mems)
__device__ float g_coreR[NT * DMODELC];    // tf32-rounded copy (GEMM input)
__device__ float g_xmem[KT * DMODELC];     // rounded
__device__ float g_q  [NT * DMODELC];
__device__ float g_qw [NT * DMODELC];      // rounded
__device__ float g_qr [NT * DMODELC];      // rounded
__device__ float g_kv [KT * 2 * DMODELC];  // rounded (epilogue)
__device__ float g_rk [KLENC * DMODELC];   // rounded (epilogue)
__device__ float g_pos[KLENC * DMODELC];   // rounded
__device__ float g_scores[67108864];
__device__ float g_bd    [67108864];
__device__ float g_probs [67108864];       // rounded
__device__ float g_vec[NT * DMODELC];      // rounded (epilogue)
__device__ float g_tmp[NT * DMODELC];
__device__ float g_h1 [NT * DINNERC];      // rounded (epilogue)
__device__ float g_logits[131072000];
__device__ bf    g_embb [NTOKC * DMODELC];
__device__ bf    g_coreb[NT * DMODELC];
// tf32-rounded weight copies
__device__ float g_wqR [NLAYERC * DMODELC * DMODELC];
__device__ float g_wkvR[NLAYERC * DMODELC * 2 * DMODELC];
__device__ float g_wrR [NLAYERC * DMODELC * DMODELC];
__device__ float g_woR [NLAYERC * DMODELC * DMODELC];
__device__ float g_w1R [NLAYERC * DMODELC * DINNERC];
__device__ float g_w2R [NLAYERC * DINNERC * DMODELC];

// ------------------------------ cp.async helpers ---------------------------
__device__ __forceinline__ void cp16(void* dst, const void* src) {
    unsigned d = (unsigned)__cvta_generic_to_shared(dst);
    asm volatile("cp.async.cg.shared.global [%0], [%1], 16;\n" :: "r"(d), "l"(src));
}
__device__ __forceinline__ void cp_commit() { asm volatile("cp.async.commit_group;\n"); }
__device__ __forceinline__ void cp_wait0()  { asm volatile("cp.async.wait_group 0;\n"); }

// ------------------------------- reductions --------------------------------
__device__ __forceinline__ float block_reduce_max(float v) {
    __shared__ float sd[256];
    int tid = threadIdx.x;
    sd[tid] = v; __syncthreads();
    #pragma unroll
    for (int s = 128; s > 0; s >>= 1) {
        if (tid < s) sd[tid] = fmaxf(sd[tid], sd[tid + s]);
        __syncthreads();
    }
    float r = sd[0]; __syncthreads();
    return r;
}
__device__ __forceinline__ float block_reduce_sum(float v) {
    __shared__ float sd[256];
    int tid = threadIdx.x;
    sd[tid] = v; __syncthreads();
    #pragma unroll
    for (int s = 128; s > 0; s >>= 1) {
        if (tid < s) sd[tid] += sd[tid + s];
        __syncthreads();
    }
    float r = sd[0]; __syncthreads();
    return r;
}

// --------------------- tf32 double-buffered wmma GEMM ----------------------
// Inputs MUST be tf32-pre-rounded fp32. No in-loop conversion.
// TB: B stored [N,K] (compute with B^T). EPI: 0 none, 1 +bias, 2 +bias+relu.
// RND: round output to tf32 (for GEMM-to-GEMM intermediates).
template<int BN, bool TB, int EPI, bool RND>
__global__ void __launch_bounds__(256) tgemm_k(
    const float* __restrict__ A, const float* __restrict__ B,
    float* __restrict__ C, const float* __restrict__ bias,
    int K, int lda, int ldb, int ldc,
    int batch2,
    long long sA1, long long sA2, long long sB1, long long sB2,
    long long sC1, long long sC2)
{
    constexpr int WARPS_N = BN / 32;
    constexpr int WARPS_M = 8 / WARPS_N;
    constexpr int MI = 128 / (WARPS_M * 16);
    constexpr int NI = 2;
    constexpr int A_LD  = 36;
    constexpr int A_ELE = 128 * A_LD;
    constexpr int B_LD  = TB ? 36 : (BN + 4);
    constexpr int B_ELE = TB ? (BN * 36) : (32 * (BN + 4));

    int z = blockIdx.z;
    int z1 = z / batch2, z2 = z - z1 * batch2;
    A += z1 * sA1 + z2 * sA2;
    B += z1 * sB1 + z2 * sB2;
    C += z1 * sC1 + z2 * sC2;

    extern __shared__ float smem[];
    float* sA[2] = { smem, smem + A_ELE };
    float* sB[2] = { smem + 2 * A_ELE, smem + 2 * A_ELE + B_ELE };
    float* stage = smem + 2 * A_ELE + 2 * B_ELE;

    const int tid  = threadIdx.x;
    const int m0   = blockIdx.y * 128, n0 = blockIdx.x * BN;
    const int warp = tid >> 5, lane = tid & 31;
    const int wm   = warp / WARPS_N, wn = warp % WARPS_N;
    const int wmB  = wm * MI * 16, wnB = wn * 32;

    wmma::fragment<wmma::accumulator, 16, 16, 8, float> acc[MI][NI];
    #pragma unroll
    for (int i = 0; i < MI; i++)
        #pragma unroll
        for (int j = 0; j < NI; j++)
            wmma::fill_fragment(acc[i][j], 0.f);

    auto loadA = [&](int buf, int k0) {
        #pragma unroll
        for (int p = 0; p < 4; p++) {
            int row = p * 32 + (tid >> 3), col = (tid & 7) * 4;
            cp16(&sA[buf][row * A_LD + col],
                 A + (long long)(m0 + row) * lda + k0 + col);
        }
    };
    auto loadB = [&](int buf, int k0) {
        if (TB) {
            #pragma unroll
            for (int p = 0; p < BN / 32; p++) {
                int row = p * 32 + (tid >> 3), col = (tid & 7) * 4;
                cp16(&sB[buf][row * B_LD + col],
                     B + (long long)(n0 + row) * ldb + k0 + col);
            }
        } else {
            constexpr int TPR = BN / 4;
            constexpr int RPP = 256 / TPR;
            #pragma unroll
            for (int p = 0; p < 32 / RPP; p++) {
                int row = p * RPP + tid / TPR;
                int col = (tid % TPR) * 4;
                cp16(&sB[buf][row * B_LD + col],
                     B + (long long)(k0 + row) * ldb + n0 + col);
            }
        }
    };
    auto compute = [&](int buf) {
        #pragma unroll
        for (int kk = 0; kk < 4; kk++) {
            wmma::fragment<wmma::matrix_a, 16, 16, 8, wmma::precision::tf32,
                           wmma::row_major> af[MI];
            #pragma unroll
            for (int i = 0; i < MI; i++)
                wmma::load_matrix_sync(af[i],
                    &sA[buf][(wmB + i * 16) * A_LD + kk * 8], A_LD);
            #pragma unroll
            for (int j = 0; j < NI; j++) {
                if (TB) {
                    wmma::fragment<wmma::matrix_b, 16, 16, 8, wmma::precision::tf32,
                                   wmma::col_major> bfg;
                    wmma::load_matrix_sync(bfg,
                        &sB[buf][(wnB + j * 16) * B_LD + kk * 8], B_LD);
                    #pragma unroll
                    for (int i = 0; i < MI; i++)
                        wmma::mma_sync(acc[i][j], af[i], bfg, acc[i][j]);
                } else {
                    wmma::fragment<wmma::matrix_b, 16, 16, 8, wmma::precision::tf32,
                                   wmma::row_major> bfg;
                    wmma::load_matrix_sync(bfg,
                        &sB[buf][(kk * 8) * B_LD + wnB + j * 16], B_LD);
                    #pragma unroll
                    for (int i = 0; i < MI; i++)
                        wmma::mma_sync(acc[i][j], af[i], bfg, acc[i][j]);
                }
            }
        }
    };

    int buf = 0;
    loadA(0, 0); loadB(0, 0); cp_commit();
    for (int k0 = 0; k0 < K; k0 += 32) {
        cp_wait0();
        __syncthreads();
        int nk = k0 + 32;
        if (nk < K) { loadA(buf ^ 1, nk); loadB(buf ^ 1, nk); }
        cp_commit();
        compute(buf);
        buf ^= 1;
    }

    if (EPI == 0 && !RND) {
        #pragma unroll
        for (int i = 0; i < MI; i++)
            #pragma unroll
            for (int j = 0; j < NI; j++) {
                int row0 = m0 + wmB + i * 16;
                int col0 = n0 + wnB + j * 16;
                wmma::store_matrix_sync(C + (long long)row0 * ldc + col0,
                                        acc[i][j], ldc, wmma::mem_row_major);
            }
    } else {
        float* st = stage + warp * 256;
        #pragma unroll
        for (int i = 0; i < MI; i++)
            #pragma unroll
            for (int j = 0; j < NI; j++) {
                int row0 = m0 + wmB + i * 16;
                int col0 = n0 + wnB + j * 16;
                wmma::store_matrix_sync(st, acc[i][j], 16, wmma::mem_row_major);
                __syncwarp();
                #pragma unroll
                for (int e = 0; e < 8; e++) {
                    int idx = lane * 8 + e;
                    int r = idx >> 4, c = idx & 15;
                    float v = st[idx];
                    int col = col0 + c;
                    if (EPI >= 1) v += bias[col];
                    if (EPI == 2) v = fmaxf(v, 0.f);
                    if (RND)      v = tf32r(v);
                    C[(long long)(row0 + r) * ldc + col] = v;
                }
                __syncwarp();
            }
    }
}

// ------------------ bf16 double-buffered GEMM (B^T), fp32 out --------------
__global__ void __launch_bounds__(256) bgemm_k(
    const bf* __restrict__ A, const bf* __restrict__ B, float* __restrict__ C,
    int K, int lda, int ldb, int ldc)
{
    __shared__ bf sA[2][128 * 40];
    __shared__ bf sB[2][128 * 40];

    const int tid  = threadIdx.x;
    const int m0   = blockIdx.y * 128, n0 = blockIdx.x * 128;
    const int warp = tid >> 5;
    const int wm   = warp >> 2, wn = warp & 3;
    const int wmB  = wm * 64, wnB = wn * 32;

    wmma::fragment<wmma::accumulator, 16, 16, 16, float> acc[4][2];
    #pragma unroll
    for (int i = 0; i < 4; i++)
        #pragma unroll
        for (int j = 0; j < 2; j++)
            wmma::fill_fragment(acc[i][j], 0.f);

    auto loadAB = [&](int buf, int k0) {
        #pragma unroll
        for (int p = 0; p < 2; p++) {
            int row = p * 64 + (tid >> 2), col = (tid & 3) * 8;
            cp16(&sA[buf][row * 40 + col],
                 A + (long long)(m0 + row) * lda + k0 + col);
            cp16(&sB[buf][row * 40 + col],
                 B + (long long)(n0 + row) * ldb + k0 + col);
        }
    };
    auto compute = [&](int buf) {
        #pragma unroll
        for (int kk = 0; kk < 2; kk++) {
            wmma::fragment<wmma::matrix_a, 16, 16, 16, bf, wmma::row_major> af[4];
            #pragma unroll
            for (int i = 0; i < 4; i++)
                wmma::load_matrix_sync(af[i], &sA[buf][(wmB + i * 16) * 40 + kk * 16], 40);
            #pragma unroll
            for (int j = 0; j < 2; j++) {
                wmma::fragment<wmma::matrix_b, 16, 16, 16, bf, wmma::col_major> bfg;
                wmma::load_matrix_sync(bfg, &sB[buf][(wnB + j * 16) * 40 + kk * 16], 40);
                #pragma unroll
                for (int i = 0; i < 4; i++)
                    wmma::mma_sync(acc[i][j], af[i], bfg, acc[i][j]);
            }
        }
    };

    int buf = 0;
    loadAB(0, 0); cp_commit();
    for (int k0 = 0; k0 < K; k0 += 32) {
        cp_wait0();
        __syncthreads();
        int nk = k0 + 32;
        if (nk < K) loadAB(buf ^ 1, nk);
        cp_commit();
        compute(buf);
        buf ^= 1;
    }

    #pragma unroll
    for (int i = 0; i < 4; i++)
        #pragma unroll
        for (int j = 0; j < 2; j++) {
            int row0 = m0 + wmB + i * 16;
            int col0 = n0 + wnB + j * 16;
            wmma::store_matrix_sync(C + (long long)row0 * ldc + col0,
                                    acc[i][j], ldc, wmma::mem_row_major);
        }
}

// ------------------------------ small kernels ------------------------------
__global__ void conv_k(const float* __restrict__ src, bf* __restrict__ dst, int n)
{
    int i = (blockIdx.x * 256 + threadIdx.x) * 4;
    if (i < n) {
        float4 v = *(const float4*)(src + i);
        dst[i + 0] = __float2bfloat16_rn(v.x);
        dst[i + 1] = __float2bfloat16_rn(v.y);
        dst[i + 2] = __float2bfloat16_rn(v.z);
        dst[i + 3] = __float2bfloat16_rn(v.w);
    }
}

// fp32 -> tf32-rounded fp32
__global__ void round_k(const float* __restrict__ src, float* __restrict__ dst, int n)
{
    int i = (blockIdx.x * 256 + threadIdx.x) * 4;
    if (i < n) {
        float4 v = *(const float4*)(src + i);
        float4 o;
        o.x = tf32r(v.x); o.y = tf32r(v.y); o.z = tf32r(v.z); o.w = tf32r(v.w);
        *(float4*)(dst + i) = o;
    }
}

__global__ void embed_k(const int* __restrict__ data, const float* __restrict__ emb,
                        float* __restrict__ core, float* __restrict__ coreR,
                        float* __restrict__ memout)
{
    int t = blockIdx.x;
    int tok = data[t];
    const float* src = emb + (long long)tok * DMODELC;
    #pragma unroll
    for (int r = 0; r < 4; r++) {
        int d = threadIdx.x + 256 * r;
        float v = src[d];
        core  [(long long)t * DMODELC + d] = v;
        coreR [(long long)t * DMODELC + d] = tf32r(v);
        memout[(long long)t * DMODELC + d] = v;
    }
}

__global__ void pos_k(float* __restrict__ pos)
{
    int k = blockIdx.x;
    float p = (float)(KLENC - 1 - k);
    #pragma unroll
    for (int r = 0; r < 4; r++) {
        int c = threadIdx.x + 256 * r;
        int j = (c < 512) ? c : (c - 512);
        float invf = 1.0f / powf(10000.0f, (2.0f * (float)j) / 1024.0f);
        float ang = p * invf;
        float v = (c < 512) ? sinf(ang) : cosf(ang);
        pos[(long long)k * DMODELC + c] = tf32r(v);
    }
}

__global__ void qwqr_k(const float* __restrict__ q, const float* __restrict__ rwb,
                       const float* __restrict__ rrb,
                       float* __restrict__ qw, float* __restrict__ qr)
{
    long long idx = (long long)blockIdx.x * 256 + threadIdx.x;
    int c = (int)(idx & 1023);
    float v = q[idx];
    qw[idx] = tf32r(v + rwb[c]);
    qr[idx] = tf32r(v + rrb[c]);
}

__global__ void softmax_k(const float* __restrict__ scores, const float* __restrict__ bd,
                          float* __restrict__ probs)
{
    int i  = blockIdx.x;
    int bn = blockIdx.y;
    int b = bn >> 4, n = bn & 15;
    const float* ac = scores + (long long)bn * (QLENC * KLENC) + (long long)i * KLENC;
    float* pr = probs + (long long)bn * (QLENC * KLENC) + (long long)i * KLENC;
    const float* bdr = bd + (long long)n * ((long long)NT * KLENC)
                          + (long long)(i * BSZC + b) * KLENC;
    int shift = QLENC - 1 - i;
    int lim = i + 512;

    float vals[4];
    float lmax = -1e30f;
    #pragma unroll
    for (int r = 0; r < 4; r++) {
        int j = threadIdx.x + 256 * r;
        float v = -1e30f;
        if (j <= lim) v = (ac[j] + bdr[j + shift]) * 0.125f;
        vals[r] = v;
        lmax = fmaxf(lmax, v);
    }
    float rmax = block_reduce_max(lmax);
    float lsum = 0.f;
    #pragma unroll
    for (int r = 0; r < 4; r++) {
        float e = expf(vals[r] - rmax);
        vals[r] = e;
        lsum += e;
    }
    float rsum = block_reduce_sum(lsum);
    float inv = 1.0f / rsum;
    #pragma unroll
    for (int r = 0; r < 4; r++) {
        int j = threadIdx.x + 256 * r;
        pr[j] = tf32r(vals[r] * inv);
    }
}

// dst = LN(x+res) exact; dstR = tf32-rounded copy; dst2 optional (mems)
__global__ void ln_k(const float* __restrict__ x, const float* __restrict__ res,
                     const float* __restrict__ g, const float* __restrict__ bb,
                     float* __restrict__ dst, float* __restrict__ dstR,
                     float* __restrict__ dst2)
{
    long long t = blockIdx.x;
    const float* xr = x   + t * DMODELC;
    const float* rr = res + t * DMODELC;
    float v[4];
    float s = 0.f, sq = 0.f;
    #pragma unroll
    for (int r = 0; r < 4; r++) {
        int d = threadIdx.x + 256 * r;
        float u = xr[d] + rr[d];
        v[r] = u; s += u; sq += u * u;
    }
    float sum  = block_reduce_sum(s);
    float sums = block_reduce_sum(sq);
    float mean = sum * (1.0f / 1024.0f);
    float var  = sums * (1.0f / 1024.0f) - mean * mean;
    float rstd = rsqrtf(var + 1e-5f);
    #pragma unroll
    for (int r = 0; r < 4; r++) {
        int d = threadIdx.x + 256 * r;
        float y = (v[r] - mean) * rstd * g[d] + bb[d];
        dst [t * DMODELC + d] = y;
        dstR[t * DMODELC + d] = tf32r(y);
        if (dst2) dst2[t * DMODELC + d] = y;
    }
}

__global__ void loss_k(const float* __restrict__ logits, const int* __restrict__ target,
                       float* __restrict__ out)
{
    int t = blockIdx.x;
    const float* lr = logits + (long long)t * NTOKC;
    float lmax = -1e30f;
    for (int j = threadIdx.x; j < NTOKC; j += 256) lmax = fmaxf(lmax, lr[j]);
    float m = block_reduce_max(lmax);
    float lsum = 0.f;
    for (int j = threadIdx.x; j < NTOKC; j += 256) lsum += expf(lr[j] - m);
    float s = block_reduce_sum(lsum);
    if (threadIdx.x == 0) {
        int tg = target[t];
        out[t] = -(lr[tg] - m - logf(s));
    }
}

// ------------------------------ host dispatch ------------------------------
template<int BN, bool TB, int EPI, bool RND>
static inline void launch_tg(const float* A, const float* B, float* C,
    const float* bias, int gx, int gy, int gz,
    int K, int lda, int ldb, int ldc,
    int batch2 = 1,
    long long sA1 = 0, long long sA2 = 0,
    long long sB1 = 0, long long sB2 = 0,
    long long sC1 = 0, long long sC2 = 0)
{
    const int A_ELE = 128 * 36;
    const int B_ELE = TB ? (BN * 36) : (32 * (BN + 4));
    int smem = (2 * A_ELE + 2 * B_ELE + 2048) * 4;
    cudaFuncSetAttribute(tgemm_k<BN, TB, EPI, RND>,
                         cudaFuncAttributeMaxDynamicSharedMemorySize, smem);
    tgemm_k<BN, TB, EPI, RND><<<dim3(gx, gy, gz), 256, smem>>>(
        A, B, C, bias, K, lda, ldb, ldc, batch2, sA1, sA2, sB1, sB2, sC1, sC2);
}

extern "C" void kernel_launch(void* const* d_in, const int* in_sizes, int n_in,
                              void* d_out, int out_size)
{
    const int*   data   = (const int*)  d_in[0];
    const int*   target = (const int*)  d_in[1];
    const float* memory = (const float*)d_in[2];
    const float* emb_W  = (const float*)d_in[3];
    const float* rwb    = (const float*)d_in[4];
    const float* rrb    = (const float*)d_in[5];
    const float* Wq     = (const float*)d_in[6];
    const float* Wkv    = (const float*)d_in[7];
    const float* Wr     = (const float*)d_in[8];
    const float* Wo     = (const float*)d_in[9];
    const float* W1     = (const float*)d_in[10];
    const float* b1     = (const float*)d_in[11];
    const float* W2     = (const float*)d_in[12];
    const float* b2     = (const float*)d_in[13];
    const float* ln1g   = (const float*)d_in[14];
    const float* ln1b   = (const float*)d_in[15];
    const float* ln2g   = (const float*)d_in[16];
    const float* ln2b   = (const float*)d_in[17];
    float* out = (float*)d_out;

    float *core, *coreR, *xmem, *q, *qw, *qr, *kv, *rk, *pos, *scores, *bdp,
          *probs, *vec, *tmp, *h1, *logits;
    float *wqR, *wkvR, *wrR, *woR, *w1R, *w2R;
    bf *embb, *coreb;
    cudaGetSymbolAddress((void**)&core,   g_core);
    cudaGetSymbolAddress((void**)&coreR,  g_coreR);
    cudaGetSymbolAddress((void**)&xmem,   g_xmem);
    cudaGetSymbolAddress((void**)&q,      g_q);
    cudaGetSymbolAddress((void**)&qw,     g_qw);
    cudaGetSymbolAddress((void**)&qr,     g_qr);
    cudaGetSymbolAddress((void**)&kv,     g_kv);
    cudaGetSymbolAddress((void**)&rk,     g_rk);
    cudaGetSymbolAddress((void**)&pos,    g_pos);
    cudaGetSymbolAddress((void**)&scores, g_scores);
    cudaGetSymbolAddress((void**)&bdp,    g_bd);
    cudaGetSymbolAddress((void**)&probs,  g_probs);
    cudaGetSymbolAddress((void**)&vec,    g_vec);
    cudaGetSymbolAddress((void**)&tmp,    g_tmp);
    cudaGetSymbolAddress((void**)&h1,     g_h1);
    cudaGetSymbolAddress((void**)&logits, g_logits);
    cudaGetSymbolAddress((void**)&wqR,    g_wqR);
    cudaGetSymbolAddress((void**)&wkvR,   g_wkvR);
    cudaGetSymbolAddress((void**)&wrR,    g_wrR);
    cudaGetSymbolAddress((void**)&woR,    g_woR);
    cudaGetSymbolAddress((void**)&w1R,    g_w1R);
    cudaGetSymbolAddress((void**)&w2R,    g_w2R);
    cudaGetSymbolAddress((void**)&embb,   g_embb);
    cudaGetSymbolAddress((void**)&coreb,  g_coreb);

    const long long LSLOT = (long long)NT * DMODELC;
    float* mems_out = out + NT;

    // one-time per-launch prep
    embed_k<<<NT, 256>>>(data, emb_W, core, coreR, mems_out);
    pos_k<<<KLENC, 256>>>(pos);
    conv_k<<<(NTOKC * DMODELC) / 1024, 256>>>(emb_W, embb, NTOKC * DMODELC);
    {
        int n;
        n = NLAYERC * DMODELC * DMODELC;     round_k<<<n / 1024, 256>>>(Wq,  wqR,  n);
        n = NLAYERC * DMODELC * 2 * DMODELC; round_k<<<n / 1024, 256>>>(Wkv, wkvR, n);
        n = NLAYERC * DMODELC * DMODELC;     round_k<<<n / 1024, 256>>>(Wr,  wrR,  n);
        n = NLAYERC * DMODELC * DMODELC;     round_k<<<n / 1024, 256>>>(Wo,  woR,  n);
        n = NLAYERC * DMODELC * DINNERC;     round_k<<<n / 1024, 256>>>(W1,  w1R,  n);
        n = NLAYERC * DINNERC * DMODELC;     round_k<<<n / 1024, 256>>>(W2,  w2R,  n);
    }

    for (int l = 0; l < NLAYERC; l++) {
        const float* Wq_l  = wqR  + (long long)l * DMODELC * DMODELC;
        const float* Wkv_l = wkvR + (long long)l * DMODELC * 2 * DMODELC;
        const float* Wr_l  = wrR  + (long long)l * DMODELC * DMODELC;
        const float* Wo_l  = woR  + (long long)l * DMODELC * DMODELC;
        const float* W1_l  = w1R  + (long long)l * DMODELC * DINNERC;
        const float* b1_l  = b1   + (long long)l * DINNERC;
        const float* W2_l  = w2R  + (long long)l * DINNERC * DMODELC;
        const float* b2_l  = b2   + (long long)l * DMODELC;

        // x_mem (rounded) = [round(memory[l]); coreR]
        round_k<<<(int)(LSLOT / 1024), 256>>>(memory + (long long)l * LSLOT,
                                              xmem, (int)LSLOT);
        cudaMemcpyAsync(xmem + LSLOT, coreR, LSLOT * sizeof(float),
                        cudaMemcpyDeviceToDevice, 0);

        // q = coreR @ Wq
        launch_tg<128, false, 0, false>(coreR, Wq_l, q, nullptr,
            DMODELC / 128, NT / 128, 1, DMODELC, DMODELC, DMODELC, DMODELC);
        qwqr_k<<<(NT * DMODELC) / 256, 256>>>(q, rwb, rrb, qw, qr);

        // kv = xmem @ Wkv  (rounded out)
        launch_tg<128, false, 0, true>(xmem, Wkv_l, kv, nullptr,
            2 * DMODELC / 128, KT / 128, 1, DMODELC, DMODELC, 2 * DMODELC, 2 * DMODELC);

        // r_k = pos @ Wr  (rounded out)
        launch_tg<128, false, 0, true>(pos, Wr_l, rk, nullptr,
            DMODELC / 128, KLENC / 128, 1, DMODELC, DMODELC, DMODELC, DMODELC);

        // AC[b,n] = qw[512,64] @ k^T
        launch_tg<128, true, 0, false>(qw, kv, scores, nullptr,
            KLENC / 128, QLENC / 128, BSZC * NHEADC,
            DHEADC, BSZC * DMODELC, BSZC * 2 * DMODELC, KLENC,
            NHEADC,
            DMODELC, DHEADC,
            2 * DMODELC, DHEADC,
            (long long)NHEADC * QLENC * KLENC, (long long)QLENC * KLENC);

        // BD_raw[n] = qr[4096,64] @ rk^T
        launch_tg<128, true, 0, false>(qr, rk, bdp, nullptr,
            KLENC / 128, NT / 128, NHEADC,
            DHEADC, DMODELC, DMODELC, KLENC,
            NHEADC,
            0, DHEADC, 0, DHEADC, 0, (long long)NT * KLENC);

        softmax_k<<<dim3(QLENC, BSZC * NHEADC), 256>>>(scores, bdp, probs);

        // vec[b,n] = probs @ v  (BN=64, rounded out)
        launch_tg<64, false, 0, true>(probs, kv + DMODELC, vec, nullptr,
            1, QLENC / 128, BSZC * NHEADC,
            KLENC, KLENC, BSZC * 2 * DMODELC, BSZC * DMODELC,
            NHEADC,
            (long long)NHEADC * QLENC * KLENC, (long long)QLENC * KLENC,
            2 * DMODELC, DHEADC,
            DMODELC, DHEADC);

        // attn_out = vec @ Wo
        launch_tg<128, false, 0, false>(vec, Wo_l, tmp, nullptr,
            DMODELC / 128, NT / 128, 1, DMODELC, DMODELC, DMODELC, DMODELC);

        ln_k<<<NT, 256>>>(core, tmp, ln1g + l * DMODELC, ln1b + l * DMODELC,
                          core, coreR, nullptr);

        // h1 = relu(coreR @ W1 + b1)  (rounded out)
        launch_tg<128, false, 2, true>(coreR, W1_l, h1, b1_l,
            DINNERC / 128, NT / 128, 1, DMODELC, DMODELC, DINNERC, DINNERC);

        // ff = h1 @ W2 + b2
        launch_tg<128, false, 1, false>(h1, W2_l, tmp, b2_l,
            DMODELC / 128, NT / 128, 1, DINNERC, DINNERC, DMODELC, DMODELC);

        float* memout = (l < NLAYERC - 1) ? (mems_out + (long long)(l + 1) * LSLOT)
                                          : nullptr;
        ln_k<<<NT, 256>>>(core, tmp, ln2g + l * DMODELC, ln2b + l * DMODELC,
                          core, coreR, memout);
    }

    // logits = coreb @ embb^T (bf16 tensor cores, loss-only path)
    conv_k<<<(NT * DMODELC) / 1024, 256>>>(core, coreb, NT * DMODELC);
    bgemm_k<<<dim3(NTOKC / 128, NT / 128, 1), 256>>>(
        coreb, embb, logits, DMODELC, DMODELC, DMODELC, NTOKC);

    loss_k<<<NT, 256>>>(logits, target, out);
}